// round 5
// baseline (speedup 1.0000x reference)
#include <cuda_runtime.h>
#include <cuda_bf16.h>

// Morphological opening (erosion then dilation), 3x3 structuring element,
// fused single pass via register-resident vertical sweep.
// Input:  d_in[0] = img  float32 [8,3,1024,1024]  (24 planes of 1024x1024)
//         d_in[1] = kernel int32 [3,3]
// Output: d_out   = float32 same shape.

#define BIGV 1e4f

constexpr int W_IMG = 1024;
constexpr int H_IMG = 1024;
constexpr int ROWS_PER_CHUNK = 64;   // output rows per thread sweep
constexpr int TPB = 128;             // threads per block (each owns 4 columns)

// masked min over (a,b,c) with mask bits (m0,m1,m2); BIGV if all masked out
static __device__ __forceinline__ float pmin3(float a, float b, float c,
                                              bool m0, bool m1, bool m2) {
    if (m0 && m1 && m2)   return fminf(fminf(a, b), c);
    if (!m0 && m1 && !m2) return b;
    float r = BIGV;
    if (m0) r = fminf(r, a);
    if (m1) r = fminf(r, b);
    if (m2) r = fminf(r, c);
    return r;
}

static __device__ __forceinline__ float pmax3(float a, float b, float c,
                                              bool m0, bool m1, bool m2) {
    if (m0 && m1 && m2)   return fmaxf(fmaxf(a, b), c);
    if (!m0 && m1 && !m2) return b;
    float r = -BIGV;
    if (m0) r = fmaxf(r, a);
    if (m1) r = fmaxf(r, b);
    if (m2) r = fmaxf(r, c);
    return r;
}

// Load 12 input floats: columns [x-4, x+8) of row g, BIGV-padded out of bounds.
// x is a multiple of 4 so all three float4 loads are 16B-aligned.
static __device__ __forceinline__ void load_row(const float* __restrict__ plane,
                                                int x, int g, float L[12]) {
    if ((unsigned)g >= (unsigned)H_IMG) {
#pragma unroll
        for (int i = 0; i < 12; i++) L[i] = BIGV;
        return;
    }
    const float* row = plane + (size_t)g * W_IMG;
    if (x >= 4) {
        float4 v = *reinterpret_cast<const float4*>(row + x - 4);
        L[0] = v.x; L[1] = v.y; L[2] = v.z; L[3] = v.w;
    } else {
        L[0] = BIGV; L[1] = BIGV; L[2] = BIGV; L[3] = BIGV;
    }
    {
        float4 v = *reinterpret_cast<const float4*>(row + x);
        L[4] = v.x; L[5] = v.y; L[6] = v.z; L[7] = v.w;
    }
    if (x + 8 <= W_IMG) {
        float4 v = *reinterpret_cast<const float4*>(row + x + 4);
        L[8] = v.x; L[9] = v.y; L[10] = v.z; L[11] = v.w;
    } else {
        L[8] = BIGV; L[9] = BIGV; L[10] = BIGV; L[11] = BIGV;
    }
}

// The sweep. Thread handles output columns [x, x+4) over rows [y0, y0+ROWS).
// Erosion row e_r (cols x-1..x+4, 6 values) needs input rows r-1..r+1
// (cols x-2..x+5, served by the 12-float load window).
// Output row ro needs e rows ro-1..ro+1.
// Per-kernel-row "patterns" (masked horizontal min/max) are computed once per
// loaded row and carried in a small register pipeline, so nothing ever touches
// shared memory.
template <bool CROSS>
static __device__ __forceinline__ void opening_sweep(const float* __restrict__ img,
                                                     float* __restrict__ out,
                                                     unsigned bits) {
    const bool m00 = CROSS ? false : ((bits >> 0) & 1);
    const bool m01 = CROSS ? true  : ((bits >> 1) & 1);
    const bool m02 = CROSS ? false : ((bits >> 2) & 1);
    const bool m10 = CROSS ? true  : ((bits >> 3) & 1);
    const bool m11 = CROSS ? true  : ((bits >> 4) & 1);
    const bool m12 = CROSS ? true  : ((bits >> 5) & 1);
    const bool m20 = CROSS ? false : ((bits >> 6) & 1);
    const bool m21 = CROSS ? true  : ((bits >> 7) & 1);
    const bool m22 = CROSS ? false : ((bits >> 8) & 1);

    const float* plane = img + (size_t)blockIdx.z * H_IMG * W_IMG;
    float* oplane      = out + (size_t)blockIdx.z * H_IMG * W_IMG;
    const int x  = 4 * (blockIdx.x * TPB + threadIdx.x);
    const int y0 = blockIdx.y * ROWS_PER_CHUNK;

    float L[12];
    // erosion pattern pipeline:
    //   p0a = P0(row r-1), p1b = P1(row r)  (P0/P1/P2 = masked hmin with mask row k)
    float p0a[6], p0b[6], p1b[6];
    // dilation pattern pipeline:
    //   q0a = Q0(e_{r-2}), q1b = Q1(e_{r-1})
    float q0a[4], q0b[4], q1b[4];
#pragma unroll
    for (int j = 0; j < 4; j++) { q0a[j] = -BIGV; q0b[j] = -BIGV; q1b[j] = -BIGV; }

    // prologue: rows y0-2 and y0-1
    load_row(plane, x, y0 - 2, L);
#pragma unroll
    for (int j = 0; j < 6; j++)
        p0a[j] = pmin3(L[j + 2], L[j + 3], L[j + 4], m00, m01, m02);
    load_row(plane, x, y0 - 1, L);
#pragma unroll
    for (int j = 0; j < 6; j++) {
        p0b[j] = pmin3(L[j + 2], L[j + 3], L[j + 4], m00, m01, m02);
        p1b[j] = pmin3(L[j + 2], L[j + 3], L[j + 4], m10, m11, m12);
    }

    // main sweep: iteration t computes erosion row r = y0-1+t and emits output
    // row r-1 once the e-row pipeline is primed.
#pragma unroll 2
    for (int t = 0; t < ROWS_PER_CHUNK + 2; ++t) {
        const int r = y0 - 1 + t;
        load_row(plane, x, r + 1, L);

        float P0n[6], P1n[6], P2n[6];
#pragma unroll
        for (int j = 0; j < 6; j++) {
            P0n[j] = pmin3(L[j + 2], L[j + 3], L[j + 4], m00, m01, m02);
            P1n[j] = pmin3(L[j + 2], L[j + 3], L[j + 4], m10, m11, m12);
            P2n[j] = pmin3(L[j + 2], L[j + 3], L[j + 4], m20, m21, m22);
        }

        // erosion row r: e[j] lives at column x-1+j.
        // Rows/cols outside the image must be -BIGV for the dilation step
        // (the eroded image is only defined on [0,H)x[0,W)).
        const bool rowok = (r >= 0) && (r < H_IMG);
        float e[6];
#pragma unroll
        for (int j = 0; j < 6; j++)
            e[j] = rowok ? fminf(fminf(p0a[j], p1b[j]), P2n[j]) : -BIGV;
        if (rowok) {
            if (x == 0)         e[0] = -BIGV;  // column -1
            if (x == W_IMG - 4) e[5] = -BIGV;  // column W
        }

        // dilation patterns of e row r (output col x+j uses e idx j..j+2)
        float Q0n[4], Q1n[4], Q2n[4];
#pragma unroll
        for (int j = 0; j < 4; j++) {
            Q0n[j] = pmax3(e[j], e[j + 1], e[j + 2], m00, m01, m02);
            Q1n[j] = pmax3(e[j], e[j + 1], e[j + 2], m10, m11, m12);
            Q2n[j] = pmax3(e[j], e[j + 1], e[j + 2], m20, m21, m22);
        }

        const int ro = r - 1;
        if (ro >= y0) {
            float4 o;
            o.x = fmaxf(fmaxf(q0a[0], q1b[0]), Q2n[0]);
            o.y = fmaxf(fmaxf(q0a[1], q1b[1]), Q2n[1]);
            o.z = fmaxf(fmaxf(q0a[2], q1b[2]), Q2n[2]);
            o.w = fmaxf(fmaxf(q0a[3], q1b[3]), Q2n[3]);
            *reinterpret_cast<float4*>(oplane + (size_t)ro * W_IMG + x) = o;
        }

        // rotate pipelines
#pragma unroll
        for (int j = 0; j < 6; j++) { p0a[j] = p0b[j]; p0b[j] = P0n[j]; p1b[j] = P1n[j]; }
#pragma unroll
        for (int j = 0; j < 4; j++) { q0a[j] = q0b[j]; q0b[j] = Q0n[j]; q1b[j] = Q1n[j]; }
    }
}

__global__ void __launch_bounds__(TPB)
Opening_13168369729580_kernel(const float* __restrict__ img,
                              const int* __restrict__ ker,
                              float* __restrict__ out) {
    // build 9-bit mask (uniform across grid; broadcast loads)
    unsigned bits = 0;
#pragma unroll
    for (int i = 0; i < 9; i++)
        bits |= (unsigned)(__ldg(ker + i) == 1) << i;

    // cross = positions {1,3,4,5,7} -> 0b010111010 = 0xBA
    if (bits == 0xBAu)
        opening_sweep<true>(img, out, bits);
    else
        opening_sweep<false>(img, out, bits);
}

extern "C" void kernel_launch(void* const* d_in, const int* in_sizes, int n_in,
                              void* d_out, int out_size) {
    const float* img = (const float*)d_in[0];
    const int*   ker = (const int*)d_in[1];
    float*       out = (float*)d_out;

    const int planes = in_sizes[0] / (H_IMG * W_IMG);  // 8*3 = 24
    dim3 grid(W_IMG / (4 * TPB), H_IMG / ROWS_PER_CHUNK, planes);  // (2,16,24)
    Opening_13168369729580_kernel<<<grid, TPB>>>(img, ker, out);
}

// round 6
// speedup vs baseline: 1.1757x; 1.1757x over previous
#include <cuda_runtime.h>
#include <cuda_bf16.h>

// Morphological opening (erosion then dilation), 3x3 structuring element,
// fused single pass via register-resident vertical sweep.
// R5: ROWS_PER_CHUNK 64->16 (grid 768->3072 for occupancy), double-buffered
// row loads (prefetch row r+2 before computing row r+1's patterns),
// streaming stores.
//
// Input:  d_in[0] = img  float32 [8,3,1024,1024]  (24 planes of 1024x1024)
//         d_in[1] = kernel int32 [3,3]
// Output: d_out   = float32 same shape.

#define BIGV 1e4f

constexpr int W_IMG = 1024;
constexpr int H_IMG = 1024;
constexpr int ROWS_PER_CHUNK = 16;   // output rows per thread sweep
constexpr int TPB = 128;             // threads per block (each owns 4 columns)

// masked min over (a,b,c) with mask bits (m0,m1,m2); BIGV if all masked out
static __device__ __forceinline__ float pmin3(float a, float b, float c,
                                              bool m0, bool m1, bool m2) {
    if (m0 && m1 && m2)   return fminf(fminf(a, b), c);
    if (!m0 && m1 && !m2) return b;
    float r = BIGV;
    if (m0) r = fminf(r, a);
    if (m1) r = fminf(r, b);
    if (m2) r = fminf(r, c);
    return r;
}

static __device__ __forceinline__ float pmax3(float a, float b, float c,
                                              bool m0, bool m1, bool m2) {
    if (m0 && m1 && m2)   return fmaxf(fmaxf(a, b), c);
    if (!m0 && m1 && !m2) return b;
    float r = -BIGV;
    if (m0) r = fmaxf(r, a);
    if (m1) r = fmaxf(r, b);
    if (m2) r = fmaxf(r, c);
    return r;
}

// Load 12 input floats: columns [x-4, x+8) of row g, BIGV-padded out of bounds.
// x is a multiple of 4 so all three float4 loads are 16B-aligned.
static __device__ __forceinline__ void load_row(const float* __restrict__ plane,
                                                int x, int g, float L[12]) {
    if ((unsigned)g >= (unsigned)H_IMG) {
#pragma unroll
        for (int i = 0; i < 12; i++) L[i] = BIGV;
        return;
    }
    const float* row = plane + (size_t)g * W_IMG;
    if (x >= 4) {
        float4 v = *reinterpret_cast<const float4*>(row + x - 4);
        L[0] = v.x; L[1] = v.y; L[2] = v.z; L[3] = v.w;
    } else {
        L[0] = BIGV; L[1] = BIGV; L[2] = BIGV; L[3] = BIGV;
    }
    {
        float4 v = *reinterpret_cast<const float4*>(row + x);
        L[4] = v.x; L[5] = v.y; L[6] = v.z; L[7] = v.w;
    }
    if (x + 8 <= W_IMG) {
        float4 v = *reinterpret_cast<const float4*>(row + x + 4);
        L[8] = v.x; L[9] = v.y; L[10] = v.z; L[11] = v.w;
    } else {
        L[8] = BIGV; L[9] = BIGV; L[10] = BIGV; L[11] = BIGV;
    }
}

// The sweep. Thread handles output columns [x, x+4) over rows [y0, y0+ROWS).
// Erosion row e_r (cols x-1..x+4, 6 values) needs input rows r-1..r+1.
// Output row ro needs e rows ro-1..ro+1.
// Pattern (masked horizontal min/max) pipelines live in registers; the raw
// row window is double-buffered so the next row's LDGs are in flight while
// the current row's patterns are computed.
template <bool CROSS>
static __device__ __forceinline__ void opening_sweep(const float* __restrict__ img,
                                                     float* __restrict__ out,
                                                     unsigned bits) {
    const bool m00 = CROSS ? false : ((bits >> 0) & 1);
    const bool m01 = CROSS ? true  : ((bits >> 1) & 1);
    const bool m02 = CROSS ? false : ((bits >> 2) & 1);
    const bool m10 = CROSS ? true  : ((bits >> 3) & 1);
    const bool m11 = CROSS ? true  : ((bits >> 4) & 1);
    const bool m12 = CROSS ? true  : ((bits >> 5) & 1);
    const bool m20 = CROSS ? false : ((bits >> 6) & 1);
    const bool m21 = CROSS ? true  : ((bits >> 7) & 1);
    const bool m22 = CROSS ? false : ((bits >> 8) & 1);

    const float* plane = img + (size_t)blockIdx.z * H_IMG * W_IMG;
    float* oplane      = out + (size_t)blockIdx.z * H_IMG * W_IMG;
    const int x  = 4 * (blockIdx.x * TPB + threadIdx.x);
    const int y0 = blockIdx.y * ROWS_PER_CHUNK;

    float Lc[12], Ln[12];
    // erosion pattern pipeline:
    //   p0a = P0(row r-1), p1b = P1(row r)
    float p0a[6], p0b[6], p1b[6];
    // dilation pattern pipeline:
    //   q0a = Q0(e_{r-2}), q1b = Q1(e_{r-1})
    float q0a[4], q0b[4], q1b[4];
#pragma unroll
    for (int j = 0; j < 4; j++) { q0a[j] = -BIGV; q0b[j] = -BIGV; q1b[j] = -BIGV; }

    // prologue: rows y0-2 and y0-1 into patterns, row y0 into Lc
    load_row(plane, x, y0 - 2, Lc);
#pragma unroll
    for (int j = 0; j < 6; j++)
        p0a[j] = pmin3(Lc[j + 2], Lc[j + 3], Lc[j + 4], m00, m01, m02);
    load_row(plane, x, y0 - 1, Lc);
#pragma unroll
    for (int j = 0; j < 6; j++) {
        p0b[j] = pmin3(Lc[j + 2], Lc[j + 3], Lc[j + 4], m00, m01, m02);
        p1b[j] = pmin3(Lc[j + 2], Lc[j + 3], Lc[j + 4], m10, m11, m12);
    }
    load_row(plane, x, y0, Lc);  // row r+1 for iteration t=0

    // iteration t: Lc holds input row r+1 (r = y0-1+t); computes erosion row r
    // and emits output row r-1 once the e-row pipeline is primed.
#pragma unroll 2
    for (int t = 0; t < ROWS_PER_CHUNK + 2; ++t) {
        const int r = y0 - 1 + t;

        // prefetch row r+2 (next iteration's Lc) while we compute on Lc
        if (t <= ROWS_PER_CHUNK)
            load_row(plane, x, r + 2, Ln);

        float P0n[6], P1n[6], P2n[6];
#pragma unroll
        for (int j = 0; j < 6; j++) {
            P0n[j] = pmin3(Lc[j + 2], Lc[j + 3], Lc[j + 4], m00, m01, m02);
            P1n[j] = pmin3(Lc[j + 2], Lc[j + 3], Lc[j + 4], m10, m11, m12);
            P2n[j] = pmin3(Lc[j + 2], Lc[j + 3], Lc[j + 4], m20, m21, m22);
        }

        // erosion row r: e[j] lives at column x-1+j.
        // Rows/cols outside the image must be -BIGV for the dilation step.
        const bool rowok = (r >= 0) && (r < H_IMG);
        float e[6];
#pragma unroll
        for (int j = 0; j < 6; j++)
            e[j] = rowok ? fminf(fminf(p0a[j], p1b[j]), P2n[j]) : -BIGV;
        if (rowok) {
            if (x == 0)         e[0] = -BIGV;  // column -1
            if (x == W_IMG - 4) e[5] = -BIGV;  // column W
        }

        // dilation patterns of e row r (output col x+j uses e idx j..j+2)
        float Q0n[4], Q1n[4], Q2n[4];
#pragma unroll
        for (int j = 0; j < 4; j++) {
            Q0n[j] = pmax3(e[j], e[j + 1], e[j + 2], m00, m01, m02);
            Q1n[j] = pmax3(e[j], e[j + 1], e[j + 2], m10, m11, m12);
            Q2n[j] = pmax3(e[j], e[j + 1], e[j + 2], m20, m21, m22);
        }

        const int ro = r - 1;
        if (ro >= y0) {
            float4 o;
            o.x = fmaxf(fmaxf(q0a[0], q1b[0]), Q2n[0]);
            o.y = fmaxf(fmaxf(q0a[1], q1b[1]), Q2n[1]);
            o.z = fmaxf(fmaxf(q0a[2], q1b[2]), Q2n[2]);
            o.w = fmaxf(fmaxf(q0a[3], q1b[3]), Q2n[3]);
            __stcs(reinterpret_cast<float4*>(oplane + (size_t)ro * W_IMG + x), o);
        }

        // rotate pattern pipelines
#pragma unroll
        for (int j = 0; j < 6; j++) { p0a[j] = p0b[j]; p0b[j] = P0n[j]; p1b[j] = P1n[j]; }
#pragma unroll
        for (int j = 0; j < 4; j++) { q0a[j] = q0b[j]; q0b[j] = Q0n[j]; q1b[j] = Q1n[j]; }
        // rotate row buffer (renamed away under unroll)
#pragma unroll
        for (int j = 0; j < 12; j++) Lc[j] = Ln[j];
    }
}

__global__ void __launch_bounds__(TPB)
Opening_13168369729580_kernel(const float* __restrict__ img,
                              const int* __restrict__ ker,
                              float* __restrict__ out) {
    // build 9-bit mask (uniform across grid; broadcast loads)
    unsigned bits = 0;
#pragma unroll
    for (int i = 0; i < 9; i++)
        bits |= (unsigned)(__ldg(ker + i) == 1) << i;

    // cross = positions {1,3,4,5,7} -> 0b010111010 = 0xBA
    if (bits == 0xBAu)
        opening_sweep<true>(img, out, bits);
    else
        opening_sweep<false>(img, out, bits);
}

extern "C" void kernel_launch(void* const* d_in, const int* in_sizes, int n_in,
                              void* d_out, int out_size) {
    const float* img = (const float*)d_in[0];
    const int*   ker = (const int*)d_in[1];
    float*       out = (float*)d_out;

    const int planes = in_sizes[0] / (H_IMG * W_IMG);  // 8*3 = 24
    dim3 grid(W_IMG / (4 * TPB), H_IMG / ROWS_PER_CHUNK, planes);  // (2,64,24)
    Opening_13168369729580_kernel<<<grid, TPB>>>(img, ker, out);
}

// round 8
// speedup vs baseline: 1.2690x; 1.0794x over previous
#include <cuda_runtime.h>
#include <cuda_bf16.h>

// Morphological opening (erosion then dilation), 3x3 structuring element.
// R6: split cross-specialized / generic kernels (each self-selects on the mask,
// so the cross kernel gets its own tight register allocation, forced to 8
// blocks/SM); exact 8-float load window (LDG.64+LDG.128+LDG.64); interior
// blocks take an unguarded template path; prefetch epilogue peeled.
//
// Input:  d_in[0] = img  float32 [8,3,1024,1024]  (24 planes of 1024x1024)
//         d_in[1] = kernel int32 [3,3]
// Output: d_out   = float32 same shape.

#define BIGV 1e4f

constexpr int W_IMG = 1024;
constexpr int H_IMG = 1024;
constexpr int ROWS  = 16;    // output rows per thread sweep
constexpr int TPB   = 128;   // threads per block; each thread owns 4 columns

// ---------------------------------------------------------------------------
// 8-wide row window: w[0..7] = input cols x-2 .. x+5 of row g.
// lok = (x>0), rok = (x<W-4): whether the left/right float2 halo is in-bounds.
// ---------------------------------------------------------------------------
static __device__ __forceinline__ void load8_u(const float* __restrict__ plane,
                                               int x, int g, bool lok, bool rok,
                                               float w[8]) {
    const float* row = plane + (size_t)g * W_IMG;
    if (lok) { float2 v = *reinterpret_cast<const float2*>(row + x - 2); w[0] = v.x; w[1] = v.y; }
    else     { w[0] = BIGV; w[1] = BIGV; }
    float4 m = *reinterpret_cast<const float4*>(row + x);
    w[2] = m.x; w[3] = m.y; w[4] = m.z; w[5] = m.w;
    if (rok) { float2 v = *reinterpret_cast<const float2*>(row + x + 4); w[6] = v.x; w[7] = v.y; }
    else     { w[6] = BIGV; w[7] = BIGV; }
}

static __device__ __forceinline__ void load8_g(const float* __restrict__ plane,
                                               int x, int g, bool lok, bool rok,
                                               float w[8]) {
    if ((unsigned)g >= (unsigned)H_IMG) {
#pragma unroll
        for (int i = 0; i < 8; i++) w[i] = BIGV;
        return;
    }
    load8_u(plane, x, g, lok, rok, w);
}

// ---------------------------------------------------------------------------
// Cross structuring element (positions {1,3,4,5,7}):
//   e_r[c]  = min(x_{r-1}[c], x_r[c-1], x_r[c], x_r[c+1], x_{r+1}[c]), OOB=+BIG
//   out_o[c]= max(e_{o-1}[c], e_o[c-1], e_o[c], e_o[c+1], e_{o+1}[c]), OOB e=-BIG
// Separate into per-row patterns carried in register pipelines:
//   v = row centers (6 wide, cols x-1..x+4), h = hmin3 (6 wide)
//   ec = e centers (4 wide, cols x..x+3),    g = hmax3 of e (4 wide)
// ---------------------------------------------------------------------------
template <bool INTERIOR>
static __device__ __forceinline__ void cross_step(
    int t, int r, bool lok, bool rok, int x, int y0,
    float* __restrict__ oplane, const float wc[8],
    float va[6], float vb[6], float hb[6],
    float ecp[4], float ecb[4], float gb[4]) {

    // patterns of input row r+1 (held in wc)
    float vn[6], hn[6];
#pragma unroll
    for (int j = 0; j < 6; j++) {
        vn[j] = wc[j + 1];
        hn[j] = fminf(fminf(wc[j], wc[j + 1]), wc[j + 2]);
    }

    // erosion row r (cols x-1..x+4); OOB rows/cols become -BIG for dilation
    const bool rowok = INTERIOR || ((unsigned)r < (unsigned)H_IMG);
    float e[6];
#pragma unroll
    for (int j = 0; j < 6; j++) {
        float ev = fminf(fminf(va[j], hb[j]), vn[j]);
        e[j] = rowok ? ev : -BIGV;
    }
    if (!lok) e[0] = -BIGV;   // column -1
    if (!rok) e[5] = -BIGV;   // column W

    // dilation patterns of e row r
    float ecn[4], gn[4];
#pragma unroll
    for (int j = 0; j < 4; j++) {
        ecn[j] = e[j + 1];
        gn[j]  = fmaxf(fmaxf(e[j], e[j + 1]), e[j + 2]);
    }

    // emit output row ro = r-1 once the e pipeline is primed (t >= 2)
    if (t >= 2) {
        const int ro = y0 + t - 2;
        float4 o;
        o.x = fmaxf(fmaxf(ecp[0], gb[0]), ecn[0]);
        o.y = fmaxf(fmaxf(ecp[1], gb[1]), ecn[1]);
        o.z = fmaxf(fmaxf(ecp[2], gb[2]), ecn[2]);
        o.w = fmaxf(fmaxf(ecp[3], gb[3]), ecn[3]);
        __stcs(reinterpret_cast<float4*>(oplane + (size_t)ro * W_IMG + x), o);
    }

    // rotate pipelines
#pragma unroll
    for (int j = 0; j < 6; j++) { va[j] = vb[j]; vb[j] = vn[j]; hb[j] = hn[j]; }
#pragma unroll
    for (int j = 0; j < 4; j++) { ecp[j] = ecb[j]; ecb[j] = ecn[j]; gb[j] = gn[j]; }
}

template <bool INTERIOR>
static __device__ __forceinline__ void sweep_cross(const float* __restrict__ plane,
                                                   float* __restrict__ oplane,
                                                   int x, int y0, bool lok, bool rok) {
    float wc[8], wn[8];
    float va[6], vb[6], hb[6];
    float ecp[4], ecb[4], gb[4];

    // prologue: rows y0-2, y0-1 into v/h pipeline; row y0 into wc
    if (INTERIOR) load8_u(plane, x, y0 - 2, lok, rok, wc);
    else          load8_g(plane, x, y0 - 2, lok, rok, wc);
#pragma unroll
    for (int j = 0; j < 6; j++) va[j] = wc[j + 1];

    if (INTERIOR) load8_u(plane, x, y0 - 1, lok, rok, wc);
    else          load8_g(plane, x, y0 - 1, lok, rok, wc);
#pragma unroll
    for (int j = 0; j < 6; j++) {
        vb[j] = wc[j + 1];
        hb[j] = fminf(fminf(wc[j], wc[j + 1]), wc[j + 2]);
    }

    if (INTERIOR) load8_u(plane, x, y0, lok, rok, wc);
    else          load8_g(plane, x, y0, lok, rok, wc);

#pragma unroll
    for (int j = 0; j < 4; j++) { ecp[j] = -BIGV; ecb[j] = -BIGV; gb[j] = -BIGV; }

    // main loop: iteration t computes erosion row r=y0-1+t from wc (row r+1),
    // prefetching row y0+t+1 into wn first.
#pragma unroll 2
    for (int t = 0; t <= ROWS; ++t) {
        const int r = y0 - 1 + t;
        if (INTERIOR) load8_u(plane, x, y0 + t + 1, lok, rok, wn);
        else          load8_g(plane, x, y0 + t + 1, lok, rok, wn);

        cross_step<INTERIOR>(t, r, lok, rok, x, y0, oplane, wc,
                             va, vb, hb, ecp, ecb, gb);
#pragma unroll
        for (int j = 0; j < 8; j++) wc[j] = wn[j];
    }
    // epilogue: t = ROWS+1, no prefetch
    cross_step<INTERIOR>(ROWS + 1, y0 + ROWS, lok, rok, x, y0, oplane, wc,
                         va, vb, hb, ecp, ecb, gb);
}

static __device__ __forceinline__ unsigned kernel_mask(const int* __restrict__ ker) {
    unsigned bits = 0;
#pragma unroll
    for (int i = 0; i < 9; i++)
        bits |= (unsigned)(__ldg(ker + i) == 1) << i;
    return bits;
}

__global__ void __launch_bounds__(TPB, 8)
Opening_cross_kernel(const float* __restrict__ img,
                     const int* __restrict__ ker,
                     float* __restrict__ out) {
    if (kernel_mask(ker) != 0xBAu) return;   // cross = 0b010111010

    const float* plane = img + (size_t)blockIdx.z * H_IMG * W_IMG;
    float* oplane      = out + (size_t)blockIdx.z * H_IMG * W_IMG;
    const int x  = 4 * (blockIdx.x * TPB + threadIdx.x);
    const int y0 = blockIdx.y * ROWS;
    const bool lok = (x > 0), rok = (x < W_IMG - 4);

    if (blockIdx.y > 0 && blockIdx.y < gridDim.y - 1)
        sweep_cross<true>(plane, oplane, x, y0, lok, rok);
    else
        sweep_cross<false>(plane, oplane, x, y0, lok, rok);
}

// ---------------------------------------------------------------------------
// Generic fallback (any 3x3 mask) — R5-proven sweep, 12-wide window.
// ---------------------------------------------------------------------------
static __device__ __forceinline__ float pmin3(float a, float b, float c,
                                              bool m0, bool m1, bool m2) {
    float r = BIGV;
    if (m0) r = fminf(r, a);
    if (m1) r = fminf(r, b);
    if (m2) r = fminf(r, c);
    return r;
}
static __device__ __forceinline__ float pmax3(float a, float b, float c,
                                              bool m0, bool m1, bool m2) {
    float r = -BIGV;
    if (m0) r = fmaxf(r, a);
    if (m1) r = fmaxf(r, b);
    if (m2) r = fmaxf(r, c);
    return r;
}

static __device__ __forceinline__ void load_row12(const float* __restrict__ plane,
                                                  int x, int g, float L[12]) {
    if ((unsigned)g >= (unsigned)H_IMG) {
#pragma unroll
        for (int i = 0; i < 12; i++) L[i] = BIGV;
        return;
    }
    const float* row = plane + (size_t)g * W_IMG;
    if (x >= 4) {
        float4 v = *reinterpret_cast<const float4*>(row + x - 4);
        L[0] = v.x; L[1] = v.y; L[2] = v.z; L[3] = v.w;
    } else { L[0] = BIGV; L[1] = BIGV; L[2] = BIGV; L[3] = BIGV; }
    { float4 v = *reinterpret_cast<const float4*>(row + x);
      L[4] = v.x; L[5] = v.y; L[6] = v.z; L[7] = v.w; }
    if (x + 8 <= W_IMG) {
        float4 v = *reinterpret_cast<const float4*>(row + x + 4);
        L[8] = v.x; L[9] = v.y; L[10] = v.z; L[11] = v.w;
    } else { L[8] = BIGV; L[9] = BIGV; L[10] = BIGV; L[11] = BIGV; }
}

__global__ void __launch_bounds__(TPB)
Opening_generic_kernel(const float* __restrict__ img,
                       const int* __restrict__ ker,
                       float* __restrict__ out) {
    const unsigned bits = kernel_mask(ker);
    if (bits == 0xBAu) return;   // cross handled by the specialized kernel

    const bool m00 = (bits >> 0) & 1, m01 = (bits >> 1) & 1, m02 = (bits >> 2) & 1;
    const bool m10 = (bits >> 3) & 1, m11 = (bits >> 4) & 1, m12 = (bits >> 5) & 1;
    const bool m20 = (bits >> 6) & 1, m21 = (bits >> 7) & 1, m22 = (bits >> 8) & 1;
    (void)m11;

    const float* plane = img + (size_t)blockIdx.z * H_IMG * W_IMG;
    float* oplane      = out + (size_t)blockIdx.z * H_IMG * W_IMG;
    const int x  = 4 * (blockIdx.x * TPB + threadIdx.x);
    const int y0 = blockIdx.y * ROWS;

    float Lc[12], Ln[12];
    float p0a[6], p0b[6], p1b[6];
    float q0a[4], q0b[4], q1b[4];
#pragma unroll
    for (int j = 0; j < 4; j++) { q0a[j] = -BIGV; q0b[j] = -BIGV; q1b[j] = -BIGV; }

    load_row12(plane, x, y0 - 2, Lc);
#pragma unroll
    for (int j = 0; j < 6; j++)
        p0a[j] = pmin3(Lc[j + 2], Lc[j + 3], Lc[j + 4], m00, m01, m02);
    load_row12(plane, x, y0 - 1, Lc);
#pragma unroll
    for (int j = 0; j < 6; j++) {
        p0b[j] = pmin3(Lc[j + 2], Lc[j + 3], Lc[j + 4], m00, m01, m02);
        p1b[j] = pmin3(Lc[j + 2], Lc[j + 3], Lc[j + 4], m10, m11, m12);
    }
    load_row12(plane, x, y0, Lc);

#pragma unroll 2
    for (int t = 0; t < ROWS + 2; ++t) {
        const int r = y0 - 1 + t;
        if (t <= ROWS) load_row12(plane, x, r + 2, Ln);

        float P0n[6], P1n[6], P2n[6];
#pragma unroll
        for (int j = 0; j < 6; j++) {
            P0n[j] = pmin3(Lc[j + 2], Lc[j + 3], Lc[j + 4], m00, m01, m02);
            P1n[j] = pmin3(Lc[j + 2], Lc[j + 3], Lc[j + 4], m10, m11, m12);
            P2n[j] = pmin3(Lc[j + 2], Lc[j + 3], Lc[j + 4], m20, m21, m22);
        }

        const bool rowok = (r >= 0) && (r < H_IMG);
        float e[6];
#pragma unroll
        for (int j = 0; j < 6; j++)
            e[j] = rowok ? fminf(fminf(p0a[j], p1b[j]), P2n[j]) : -BIGV;
        if (rowok) {
            if (x == 0)         e[0] = -BIGV;
            if (x == W_IMG - 4) e[5] = -BIGV;
        }

        float Q0n[4], Q1n[4], Q2n[4];
#pragma unroll
        for (int j = 0; j < 4; j++) {
            Q0n[j] = pmax3(e[j], e[j + 1], e[j + 2], m00, m01, m02);
            Q1n[j] = pmax3(e[j], e[j + 1], e[j + 2], m10, m11, m12);
            Q2n[j] = pmax3(e[j], e[j + 1], e[j + 2], m20, m21, m22);
        }

        const int ro = r - 1;
        if (ro >= y0) {
            float4 o;
            o.x = fmaxf(fmaxf(q0a[0], q1b[0]), Q2n[0]);
            o.y = fmaxf(fmaxf(q0a[1], q1b[1]), Q2n[1]);
            o.z = fmaxf(fmaxf(q0a[2], q1b[2]), Q2n[2]);
            o.w = fmaxf(fmaxf(q0a[3], q1b[3]), Q2n[3]);
            __stcs(reinterpret_cast<float4*>(oplane + (size_t)ro * W_IMG + x), o);
        }

#pragma unroll
        for (int j = 0; j < 6; j++) { p0a[j] = p0b[j]; p0b[j] = P0n[j]; p1b[j] = P1n[j]; }
#pragma unroll
        for (int j = 0; j < 4; j++) { q0a[j] = q0b[j]; q0b[j] = Q0n[j]; q1b[j] = Q1n[j]; }
#pragma unroll
        for (int j = 0; j < 12; j++) Lc[j] = Ln[j];
    }
}

extern "C" void kernel_launch(void* const* d_in, const int* in_sizes, int n_in,
                              void* d_out, int out_size) {
    const float* img = (const float*)d_in[0];
    const int*   ker = (const int*)d_in[1];
    float*       out = (float*)d_out;

    const int planes = in_sizes[0] / (H_IMG * W_IMG);  // 8*3 = 24
    dim3 grid(W_IMG / (4 * TPB), H_IMG / ROWS, planes);  // (2, 64, 24)
    Opening_cross_kernel<<<grid, TPB>>>(img, ker, out);
    Opening_generic_kernel<<<grid, TPB>>>(img, ker, out);
}

// round 10
// speedup vs baseline: 1.4679x; 1.1568x over previous
#include <cuda_runtime.h>
#include <cuda_bf16.h>

// Morphological opening (erosion then dilation), 3x3 structuring element.
// R8: single kernel, uniform device-side branch on the structuring-element
// mask (kills the 5.5us dead fallback launch of R7). Generic path rewritten
// onto the same exact 8-float load window as the cross path (cols x-2..x+5),
// so the merged kernel stays within 64 regs at __launch_bounds__(128, 8).
//
// Input:  d_in[0] = img  float32 [8,3,1024,1024]  (24 planes of 1024x1024)
//         d_in[1] = kernel int32 [3,3]
// Output: d_out   = float32 same shape.

#define BIGV 1e4f

constexpr int W_IMG = 1024;
constexpr int H_IMG = 1024;
constexpr int ROWS  = 16;    // output rows per thread sweep
constexpr int TPB   = 128;   // threads per block; each thread owns 4 columns

// ---------------------------------------------------------------------------
// 8-wide row window: w[0..7] = input cols x-2 .. x+5 of row g.
// lok = (x>0), rok = (x<W-4): whether the left/right float2 halo is in-bounds.
// ---------------------------------------------------------------------------
static __device__ __forceinline__ void load8_u(const float* __restrict__ plane,
                                               int x, int g, bool lok, bool rok,
                                               float w[8]) {
    const float* row = plane + (size_t)g * W_IMG;
    if (lok) { float2 v = *reinterpret_cast<const float2*>(row + x - 2); w[0] = v.x; w[1] = v.y; }
    else     { w[0] = BIGV; w[1] = BIGV; }
    float4 m = *reinterpret_cast<const float4*>(row + x);
    w[2] = m.x; w[3] = m.y; w[4] = m.z; w[5] = m.w;
    if (rok) { float2 v = *reinterpret_cast<const float2*>(row + x + 4); w[6] = v.x; w[7] = v.y; }
    else     { w[6] = BIGV; w[7] = BIGV; }
}

static __device__ __forceinline__ void load8_g(const float* __restrict__ plane,
                                               int x, int g, bool lok, bool rok,
                                               float w[8]) {
    if ((unsigned)g >= (unsigned)H_IMG) {
#pragma unroll
        for (int i = 0; i < 8; i++) w[i] = BIGV;
        return;
    }
    load8_u(plane, x, g, lok, rok, w);
}

// ===========================================================================
// Cross structuring element (positions {1,3,4,5,7}):
//   e_r[c]  = min(x_{r-1}[c], x_r[c-1], x_r[c], x_r[c+1], x_{r+1}[c]), OOB=+BIG
//   out_o[c]= max(e_{o-1}[c], e_o[c-1], e_o[c], e_o[c+1], e_{o+1}[c]), OOB e=-BIG
// Per-row patterns carried in register pipelines:
//   v = row centers (6 wide, cols x-1..x+4), h = hmin3 (6 wide)
//   ec = e centers (4 wide, cols x..x+3),    g = hmax3 of e (4 wide)
// ===========================================================================
template <bool INTERIOR>
static __device__ __forceinline__ void cross_step(
    int t, int r, bool lok, bool rok, int x, int y0,
    float* __restrict__ oplane, const float wc[8],
    float va[6], float vb[6], float hb[6],
    float ecp[4], float ecb[4], float gb[4]) {

    // patterns of input row r+1 (held in wc)
    float vn[6], hn[6];
#pragma unroll
    for (int j = 0; j < 6; j++) {
        vn[j] = wc[j + 1];
        hn[j] = fminf(fminf(wc[j], wc[j + 1]), wc[j + 2]);
    }

    // erosion row r (cols x-1..x+4); OOB rows/cols become -BIG for dilation
    const bool rowok = INTERIOR || ((unsigned)r < (unsigned)H_IMG);
    float e[6];
#pragma unroll
    for (int j = 0; j < 6; j++) {
        float ev = fminf(fminf(va[j], hb[j]), vn[j]);
        e[j] = rowok ? ev : -BIGV;
    }
    if (!lok) e[0] = -BIGV;   // column -1
    if (!rok) e[5] = -BIGV;   // column W

    // dilation patterns of e row r
    float ecn[4], gn[4];
#pragma unroll
    for (int j = 0; j < 4; j++) {
        ecn[j] = e[j + 1];
        gn[j]  = fmaxf(fmaxf(e[j], e[j + 1]), e[j + 2]);
    }

    // emit output row ro = r-1 once the e pipeline is primed (t >= 2)
    if (t >= 2) {
        const int ro = y0 + t - 2;
        float4 o;
        o.x = fmaxf(fmaxf(ecp[0], gb[0]), ecn[0]);
        o.y = fmaxf(fmaxf(ecp[1], gb[1]), ecn[1]);
        o.z = fmaxf(fmaxf(ecp[2], gb[2]), ecn[2]);
        o.w = fmaxf(fmaxf(ecp[3], gb[3]), ecn[3]);
        __stcs(reinterpret_cast<float4*>(oplane + (size_t)ro * W_IMG + x), o);
    }

    // rotate pipelines
#pragma unroll
    for (int j = 0; j < 6; j++) { va[j] = vb[j]; vb[j] = vn[j]; hb[j] = hn[j]; }
#pragma unroll
    for (int j = 0; j < 4; j++) { ecp[j] = ecb[j]; ecb[j] = ecn[j]; gb[j] = gn[j]; }
}

template <bool INTERIOR>
static __device__ __forceinline__ void sweep_cross(const float* __restrict__ plane,
                                                   float* __restrict__ oplane,
                                                   int x, int y0, bool lok, bool rok) {
    float wc[8], wn[8];
    float va[6], vb[6], hb[6];
    float ecp[4], ecb[4], gb[4];

    // prologue: rows y0-2, y0-1 into v/h pipeline; row y0 into wc
    if (INTERIOR) load8_u(plane, x, y0 - 2, lok, rok, wc);
    else          load8_g(plane, x, y0 - 2, lok, rok, wc);
#pragma unroll
    for (int j = 0; j < 6; j++) va[j] = wc[j + 1];

    if (INTERIOR) load8_u(plane, x, y0 - 1, lok, rok, wc);
    else          load8_g(plane, x, y0 - 1, lok, rok, wc);
#pragma unroll
    for (int j = 0; j < 6; j++) {
        vb[j] = wc[j + 1];
        hb[j] = fminf(fminf(wc[j], wc[j + 1]), wc[j + 2]);
    }

    if (INTERIOR) load8_u(plane, x, y0, lok, rok, wc);
    else          load8_g(plane, x, y0, lok, rok, wc);

#pragma unroll
    for (int j = 0; j < 4; j++) { ecp[j] = -BIGV; ecb[j] = -BIGV; gb[j] = -BIGV; }

    // main loop: iteration t computes erosion row r=y0-1+t from wc (row r+1),
    // prefetching row y0+t+1 into wn first.
#pragma unroll 2
    for (int t = 0; t <= ROWS; ++t) {
        const int r = y0 - 1 + t;
        if (INTERIOR) load8_u(plane, x, y0 + t + 1, lok, rok, wn);
        else          load8_g(plane, x, y0 + t + 1, lok, rok, wn);

        cross_step<INTERIOR>(t, r, lok, rok, x, y0, oplane, wc,
                             va, vb, hb, ecp, ecb, gb);
#pragma unroll
        for (int j = 0; j < 8; j++) wc[j] = wn[j];
    }
    // epilogue: t = ROWS+1, no prefetch
    cross_step<INTERIOR>(ROWS + 1, y0 + ROWS, lok, rok, x, y0, oplane, wc,
                         va, vb, hb, ecp, ecb, gb);
}

// ===========================================================================
// Generic path (any 3x3 mask) — same pipeline structure, same 8-wide window
// (cols x-2..x+5), with runtime-masked horizontal min/max.
// ===========================================================================
static __device__ __forceinline__ float pmin3(float a, float b, float c,
                                              bool m0, bool m1, bool m2) {
    float r = BIGV;
    if (m0) r = fminf(r, a);
    if (m1) r = fminf(r, b);
    if (m2) r = fminf(r, c);
    return r;
}
static __device__ __forceinline__ float pmax3(float a, float b, float c,
                                              bool m0, bool m1, bool m2) {
    float r = -BIGV;
    if (m0) r = fmaxf(r, a);
    if (m1) r = fmaxf(r, b);
    if (m2) r = fmaxf(r, c);
    return r;
}

static __device__ __forceinline__ void sweep_generic(const float* __restrict__ plane,
                                                     float* __restrict__ oplane,
                                                     int x, int y0, bool lok, bool rok,
                                                     unsigned bits) {
    const bool m00 = (bits >> 0) & 1, m01 = (bits >> 1) & 1, m02 = (bits >> 2) & 1;
    const bool m10 = (bits >> 3) & 1, m11 = (bits >> 4) & 1, m12 = (bits >> 5) & 1;
    const bool m20 = (bits >> 6) & 1, m21 = (bits >> 7) & 1, m22 = (bits >> 8) & 1;

    float wc[8], wn[8];
    float p0a[6], p0b[6], p1b[6];   // P0(r-1), P0(r), P1(r)
    float q0a[4], q0b[4], q1b[4];   // Q0(e_{r-2}), Q0(e_{r-1}), Q1(e_{r-1})
#pragma unroll
    for (int j = 0; j < 4; j++) { q0a[j] = -BIGV; q0b[j] = -BIGV; q1b[j] = -BIGV; }

    load8_g(plane, x, y0 - 2, lok, rok, wc);
#pragma unroll
    for (int j = 0; j < 6; j++)
        p0a[j] = pmin3(wc[j], wc[j + 1], wc[j + 2], m00, m01, m02);
    load8_g(plane, x, y0 - 1, lok, rok, wc);
#pragma unroll
    for (int j = 0; j < 6; j++) {
        p0b[j] = pmin3(wc[j], wc[j + 1], wc[j + 2], m00, m01, m02);
        p1b[j] = pmin3(wc[j], wc[j + 1], wc[j + 2], m10, m11, m12);
    }
    load8_g(plane, x, y0, lok, rok, wc);

#pragma unroll 2
    for (int t = 0; t < ROWS + 2; ++t) {
        const int r = y0 - 1 + t;
        if (t <= ROWS) load8_g(plane, x, r + 2, lok, rok, wn);

        float P0n[6], P1n[6], P2n[6];
#pragma unroll
        for (int j = 0; j < 6; j++) {
            P0n[j] = pmin3(wc[j], wc[j + 1], wc[j + 2], m00, m01, m02);
            P1n[j] = pmin3(wc[j], wc[j + 1], wc[j + 2], m10, m11, m12);
            P2n[j] = pmin3(wc[j], wc[j + 1], wc[j + 2], m20, m21, m22);
        }
        // middle-row erosion term: center column with m11 honored
        // (p1b already folds m10/m11/m12 of row r)
        (void)m11;

        const bool rowok = (r >= 0) && (r < H_IMG);
        float e[6];
#pragma unroll
        for (int j = 0; j < 6; j++) {
            float ev = fminf(fminf(p0a[j], p1b[j]), P2n[j]);
            e[j] = rowok ? ev : -BIGV;
        }
        if (!lok) e[0] = -BIGV;
        if (!rok) e[5] = -BIGV;

        float Q0n[4], Q1n[4], Q2n[4];
#pragma unroll
        for (int j = 0; j < 4; j++) {
            Q0n[j] = pmax3(e[j], e[j + 1], e[j + 2], m00, m01, m02);
            Q1n[j] = pmax3(e[j], e[j + 1], e[j + 2], m10, m11, m12);
            Q2n[j] = pmax3(e[j], e[j + 1], e[j + 2], m20, m21, m22);
        }

        const int ro = r - 1;
        if (ro >= y0) {
            float4 o;
            o.x = fmaxf(fmaxf(q0a[0], q1b[0]), Q2n[0]);
            o.y = fmaxf(fmaxf(q0a[1], q1b[1]), Q2n[1]);
            o.z = fmaxf(fmaxf(q0a[2], q1b[2]), Q2n[2]);
            o.w = fmaxf(fmaxf(q0a[3], q1b[3]), Q2n[3]);
            __stcs(reinterpret_cast<float4*>(oplane + (size_t)ro * W_IMG + x), o);
        }

#pragma unroll
        for (int j = 0; j < 6; j++) { p0a[j] = p0b[j]; p0b[j] = P0n[j]; p1b[j] = P1n[j]; }
#pragma unroll
        for (int j = 0; j < 4; j++) { q0a[j] = q0b[j]; q0b[j] = Q0n[j]; q1b[j] = Q1n[j]; }
#pragma unroll
        for (int j = 0; j < 8; j++) wc[j] = wn[j];
    }
}

// ===========================================================================
__global__ void __launch_bounds__(TPB, 8)
Opening_13168369729580_kernel(const float* __restrict__ img,
                              const int* __restrict__ ker,
                              float* __restrict__ out) {
    // 9-bit structuring-element mask (uniform; broadcast loads)
    unsigned bits = 0;
#pragma unroll
    for (int i = 0; i < 9; i++)
        bits |= (unsigned)(__ldg(ker + i) == 1) << i;

    const float* plane = img + (size_t)blockIdx.z * H_IMG * W_IMG;
    float* oplane      = out + (size_t)blockIdx.z * H_IMG * W_IMG;
    const int x  = 4 * (blockIdx.x * TPB + threadIdx.x);
    const int y0 = blockIdx.y * ROWS;
    const bool lok = (x > 0), rok = (x < W_IMG - 4);

    if (bits == 0xBAu) {   // cross = 0b010111010
        if (blockIdx.y > 0 && blockIdx.y < gridDim.y - 1)
            sweep_cross<true>(plane, oplane, x, y0, lok, rok);
        else
            sweep_cross<false>(plane, oplane, x, y0, lok, rok);
    } else {
        sweep_generic(plane, oplane, x, y0, lok, rok, bits);
    }
}

extern "C" void kernel_launch(void* const* d_in, const int* in_sizes, int n_in,
                              void* d_out, int out_size) {
    const float* img = (const float*)d_in[0];
    const int*   ker = (const int*)d_in[1];
    float*       out = (float*)d_out;

    const int planes = in_sizes[0] / (H_IMG * W_IMG);  // 8*3 = 24
    dim3 grid(W_IMG / (4 * TPB), H_IMG / ROWS, planes);  // (2, 64, 24)
    Opening_13168369729580_kernel<<<grid, TPB>>>(img, ker, out);
}